// round 5
// baseline (speedup 1.0000x reference)
#include <cuda_runtime.h>
#include <cuda_bf16.h>
#include <math.h>
#include <stdint.h>

// Shapes (fixed by setup_inputs)
#define B_  4
#define C_  64
#define H_  128
#define W_  128
#define HW  (H_*W_)          // 16384
#define OCF 576              // f_conv output channels = C*9
#define KTOT 576             // 64*9 reduction size

// Scratch (__device__ globals: allocation-free rule)
__device__ float g_psff[B_ * OCF * HW];   // 151 MB
__device__ float g_off[B_ * 18 * HW];
__device__ float g_m[B_ * 9 * HW];
// interleaved bf16-split weights: uint2 {hi_pair, lo_pair} at [(s*32+icp)*OCF + oc]
__device__ uint2 g_w2[9 * 32 * OCF];

__device__ __forceinline__ uint32_t pack_bf16(__nv_bfloat16 lo, __nv_bfloat16 hi) {
    uint32_t l = (uint32_t)__bfloat16_as_ushort(lo);
    uint32_t h = (uint32_t)__bfloat16_as_ushort(hi);
    return l | (h << 16);
}

__device__ __forceinline__ void mma_bf16(float* c,
        uint32_t a0, uint32_t a1, uint32_t a2, uint32_t a3,
        uint32_t b0, uint32_t b1) {
    asm volatile(
        "mma.sync.aligned.m16n8k16.row.col.f32.bf16.bf16.f32 "
        "{%0,%1,%2,%3}, {%4,%5,%6,%7}, {%8,%9}, {%0,%1,%2,%3};"
        : "+f"(c[0]), "+f"(c[1]), "+f"(c[2]), "+f"(c[3])
        : "r"(a0), "r"(a1), "r"(a2), "r"(a3), "r"(b0), "r"(b1));
}

// ---------------------------------------------------------------------------
// K0: split f_conv_w into bf16 hi/lo, ic-pair packed, hi/lo interleaved uint2.
// k = tap*64 + ic (ic fastest within tap).
// ---------------------------------------------------------------------------
__global__ void weight_split_kernel(const float* __restrict__ wgt) {
    int idx = blockIdx.x * blockDim.x + threadIdx.x;   // over 9*32*576
    if (idx >= 9 * 32 * OCF) return;
    int oc = idx % OCF;
    int tmp = idx / OCF;
    int icp = tmp & 31;
    int s = tmp >> 5;
    float w0 = wgt[oc * KTOT + (2 * icp) * 9 + s];
    float w1 = wgt[oc * KTOT + (2 * icp + 1) * 9 + s];
    __nv_bfloat16 h0 = __float2bfloat16(w0);
    __nv_bfloat16 h1 = __float2bfloat16(w1);
    __nv_bfloat16 l0 = __float2bfloat16(w0 - __bfloat162float(h0));
    __nv_bfloat16 l1 = __float2bfloat16(w1 - __bfloat162float(h1));
    g_w2[idx] = make_uint2(pack_bf16(h0, h1), pack_bf16(l0, l1));
}

// ---------------------------------------------------------------------------
// K1: merged small conv3x3: 27 outputs = 18 offset channels + 9 mask (sigmoid).
// One block per (b,h) row, 128 threads (one per w). IC chunked by 16.
// ---------------------------------------------------------------------------
#define OCM  27
#define OCMP 28
__global__ void conv_small_merged_kernel(const float* __restrict__ in,
                                         const float* __restrict__ p_w,
                                         const float* __restrict__ p_b,
                                         const float* __restrict__ m_w,
                                         const float* __restrict__ m_b) {
    const int bh = blockIdx.x;
    const int b = bh >> 7;
    const int h = bh & 127;
    const int tid = threadIdx.x;      // 128 threads, tid == w
    const int w = tid;

    __shared__ __align__(16) float sIn[16 * 3 * 132];
    __shared__ __align__(16) float sW[144 * OCMP];

    float acc[OCMP];
#pragma unroll
    for (int i = 0; i < OCMP; i++) acc[i] = 0.f;

    const float* inb = in + b * C_ * HW;

    for (int chunk = 0; chunk < 4; chunk++) {
        for (int idx = tid; idx < 144 * OCMP; idx += 128) sW[idx] = 0.f;
        __syncthreads();
        for (int idx = tid; idx < 16 * 3 * 130; idx += 128) {
            int ic = idx / 390;
            int rem = idx - ic * 390;
            int r = rem / 130;
            int cc = rem - r * 130;
            int gh = h + r - 1;
            int gw = cc - 1;
            float v = 0.f;
            if ((unsigned)gh < 128u && (unsigned)gw < 128u)
                v = inb[(chunk * 16 + ic) * HW + gh * 128 + gw];
            sIn[(ic * 3 + r) * 132 + cc] = v;
        }
        for (int idx = tid; idx < 144 * OCM; idx += 128) {
            int oc = idx / 144;
            int k = idx - oc * 144;
            float wv = (oc < 18) ? p_w[oc * KTOT + chunk * 144 + k]
                                 : m_w[(oc - 18) * KTOT + chunk * 144 + k];
            sW[k * OCMP + oc] = wv;
        }
        __syncthreads();

#pragma unroll 4
        for (int ic = 0; ic < 16; ic++) {
#pragma unroll
            for (int r = 0; r < 3; r++) {
                float v0 = sIn[(ic * 3 + r) * 132 + w];
                float v1 = sIn[(ic * 3 + r) * 132 + w + 1];
                float v2 = sIn[(ic * 3 + r) * 132 + w + 2];
#pragma unroll
                for (int dw = 0; dw < 3; dw++) {
                    float v = (dw == 0) ? v0 : ((dw == 1) ? v1 : v2);
                    const float4* wp = (const float4*)&sW[(ic * 9 + r * 3 + dw) * OCMP];
#pragma unroll
                    for (int o4 = 0; o4 < OCMP / 4; o4++) {
                        float4 wv = wp[o4];
                        acc[o4 * 4 + 0] += v * wv.x;
                        acc[o4 * 4 + 1] += v * wv.y;
                        acc[o4 * 4 + 2] += v * wv.z;
                        acc[o4 * 4 + 3] += v * wv.w;
                    }
                }
            }
        }
        __syncthreads();
    }

#pragma unroll
    for (int oc = 0; oc < 18; oc++)
        g_off[((b * 18 + oc) * 128 + h) * 128 + w] = acc[oc] + p_b[oc];
#pragma unroll
    for (int oc = 0; oc < 9; oc++) {
        float v = acc[18 + oc] + m_b[oc];
        g_m[((b * 9 + oc) * 128 + h) * 128 + w] = 1.f / (1.f + expf(-v));
    }
}

// ---------------------------------------------------------------------------
// K2: psff conv as bf16-split tensor-core implicit GEMM, smem-staged weights.
// CTA: one (b,h) row (128 px) x 64 ocs. 8 warps, warp tile 32px x 32oc.
// A tile (activations): uint2 {hi,lo} pairs, layout [r][icp][col], icp-stride
// 132 uint2 -> conflict-free LDS.64 fragments.
// B tile (weights): uint2 {hi,lo}, layout [kp_local][oc], row stride 68 uint2,
// staged per chunk in 2 phases (taps 0-3, taps 4-8) to fit 46KB static smem.
// 3 MMAs per tile: ah*bh + ah*bl + al*bh.
// ---------------------------------------------------------------------------
__global__ __launch_bounds__(256) void conv_big_mma_kernel(
        const float* __restrict__ in,
        const float* __restrict__ bias) {
    const int oc0 = blockIdx.x * 64;          // 9 tiles
    const int bh = blockIdx.y;
    const int b = bh >> 7;
    const int h = bh & 127;
    const int tid = threadIdx.x;
    const int warp = tid >> 5;
    const int lane = tid & 31;
    const int g = lane >> 2;                  // 0..7
    const int t = lane & 3;                   // 0..3
    const int wx = warp & 1;                  // oc half
    const int wy = warp >> 1;                 // px quarter
    const int px0 = wy * 32;
    const int ocb = oc0 + wx * 32;

    __shared__ __align__(16) uint2 sA[3 * 8 * 132];   // 25.3 KB
    __shared__ __align__(16) uint2 sB[40 * 68];       // 21.3 KB

    float acc[2][4][4];
#pragma unroll
    for (int mt = 0; mt < 2; mt++)
#pragma unroll
        for (int nt = 0; nt < 4; nt++)
#pragma unroll
            for (int q = 0; q < 4; q++) acc[mt][nt][q] = 0.f;

    const float* inb = in + b * C_ * HW;

    for (int chunk = 0; chunk < 4; chunk++) {
        __syncthreads();
        // stage A: 8 ic-pairs x 3 rows x 130 cols, bf16 hi/lo interleaved
        for (int idx = tid; idx < 8 * 3 * 130; idx += 256) {
            int icp = idx / 390;
            int rem = idx - icp * 390;
            int r = rem / 130;
            int cc = rem - r * 130;
            int gh = h + r - 1;
            int gw = cc - 1;
            float v0 = 0.f, v1 = 0.f;
            if ((unsigned)gh < 128u && (unsigned)gw < 128u) {
                const float* p = inb + (chunk * 16 + 2 * icp) * HW + gh * 128 + gw;
                v0 = p[0];
                v1 = p[HW];
            }
            __nv_bfloat16 h0 = __float2bfloat16(v0);
            __nv_bfloat16 h1 = __float2bfloat16(v1);
            __nv_bfloat16 l0 = __float2bfloat16(v0 - __bfloat162float(h0));
            __nv_bfloat16 l1 = __float2bfloat16(v1 - __bfloat162float(h1));
            sA[r * 1056 + icp * 132 + cc] = make_uint2(pack_bf16(h0, h1), pack_bf16(l0, l1));
        }
        // stage B phase 0: taps 0..3 -> 32 rows of 64 uint2 (+4 pad)
        for (int u = tid; u < 32 * 32; u += 256) {
            int row = u >> 5;
            int o4 = u & 31;
            int s = row >> 3;
            int icp_l = row & 7;
            int kp = s * 32 + chunk * 8 + icp_l;
            const uint4* src = (const uint4*)(g_w2 + kp * OCF + oc0);
            *(uint4*)&sB[row * 68 + o4 * 2] = src[o4];
        }
        __syncthreads();

#pragma unroll
        for (int s = 0; s < 4; s++) {
            const int r = s / 3;
            const int dw = s - 3 * r;
            uint32_t ah[2][4], al[2][4];
#pragma unroll
            for (int mt = 0; mt < 2; mt++) {
                int cb = px0 + mt * 16 + g + dw;
                uint2 q0 = sA[r * 1056 + t * 132 + cb];
                uint2 q1 = sA[r * 1056 + t * 132 + cb + 8];
                uint2 q2 = sA[r * 1056 + (t + 4) * 132 + cb];
                uint2 q3 = sA[r * 1056 + (t + 4) * 132 + cb + 8];
                ah[mt][0] = q0.x; al[mt][0] = q0.y;
                ah[mt][1] = q1.x; al[mt][1] = q1.y;
                ah[mt][2] = q2.x; al[mt][2] = q2.y;
                ah[mt][3] = q3.x; al[mt][3] = q3.y;
            }
#pragma unroll
            for (int nt = 0; nt < 4; nt++) {
                uint2 p0 = sB[(s * 8 + t) * 68 + wx * 32 + nt * 8 + g];
                uint2 p1 = sB[(s * 8 + t + 4) * 68 + wx * 32 + nt * 8 + g];
#pragma unroll
                for (int mt = 0; mt < 2; mt++) {
                    mma_bf16(acc[mt][nt], ah[mt][0], ah[mt][1], ah[mt][2], ah[mt][3], p0.x, p1.x);
                    mma_bf16(acc[mt][nt], ah[mt][0], ah[mt][1], ah[mt][2], ah[mt][3], p0.y, p1.y);
                    mma_bf16(acc[mt][nt], al[mt][0], al[mt][1], al[mt][2], al[mt][3], p0.x, p1.x);
                }
            }
        }
        __syncthreads();

        // stage B phase 1: taps 4..8 -> 40 rows
        for (int u = tid; u < 40 * 32; u += 256) {
            int row = u >> 5;
            int o4 = u & 31;
            int s = 4 + (row >> 3);
            int icp_l = row & 7;
            int kp = s * 32 + chunk * 8 + icp_l;
            const uint4* src = (const uint4*)(g_w2 + kp * OCF + oc0);
            *(uint4*)&sB[row * 68 + o4 * 2] = src[o4];
        }
        __syncthreads();

#pragma unroll
        for (int s = 4; s < 9; s++) {
            const int r = s / 3;
            const int dw = s - 3 * r;
            const int rb = (s - 4) * 8;
            uint32_t ah[2][4], al[2][4];
#pragma unroll
            for (int mt = 0; mt < 2; mt++) {
                int cb = px0 + mt * 16 + g + dw;
                uint2 q0 = sA[r * 1056 + t * 132 + cb];
                uint2 q1 = sA[r * 1056 + t * 132 + cb + 8];
                uint2 q2 = sA[r * 1056 + (t + 4) * 132 + cb];
                uint2 q3 = sA[r * 1056 + (t + 4) * 132 + cb + 8];
                ah[mt][0] = q0.x; al[mt][0] = q0.y;
                ah[mt][1] = q1.x; al[mt][1] = q1.y;
                ah[mt][2] = q2.x; al[mt][2] = q2.y;
                ah[mt][3] = q3.x; al[mt][3] = q3.y;
            }
#pragma unroll
            for (int nt = 0; nt < 4; nt++) {
                uint2 p0 = sB[(rb + t) * 68 + wx * 32 + nt * 8 + g];
                uint2 p1 = sB[(rb + t + 4) * 68 + wx * 32 + nt * 8 + g];
#pragma unroll
                for (int mt = 0; mt < 2; mt++) {
                    mma_bf16(acc[mt][nt], ah[mt][0], ah[mt][1], ah[mt][2], ah[mt][3], p0.x, p1.x);
                    mma_bf16(acc[mt][nt], ah[mt][0], ah[mt][1], ah[mt][2], ah[mt][3], p0.y, p1.y);
                    mma_bf16(acc[mt][nt], al[mt][0], al[mt][1], al[mt][2], al[mt][3], p0.x, p1.x);
                }
            }
        }
    }

    // epilogue: add bias, store to g_psff[oc][b,h,px]
    float* psb = g_psff + (size_t)b * OCF * HW + h * 128;
#pragma unroll
    for (int nt = 0; nt < 4; nt++) {
        int oc_a = ocb + nt * 8 + 2 * t;
        int oc_b = oc_a + 1;
        float bva = __ldg(&bias[oc_a]);
        float bvb = __ldg(&bias[oc_b]);
#pragma unroll
        for (int mt = 0; mt < 2; mt++) {
            int px = px0 + mt * 16 + g;
            psb[(size_t)oc_a * HW + px]     = acc[mt][nt][0] + bva;
            psb[(size_t)oc_b * HW + px]     = acc[mt][nt][1] + bvb;
            psb[(size_t)oc_a * HW + px + 8] = acc[mt][nt][2] + bva;
            psb[(size_t)oc_b * HW + px + 8] = acc[mt][nt][3] + bvb;
        }
    }
}

// ---------------------------------------------------------------------------
// K3: deformable sampling + modulation + 9-term reduce.
// ---------------------------------------------------------------------------
__global__ __launch_bounds__(256) void epilogue_kernel(
        const float* __restrict__ x,
        float* __restrict__ out) {
    const int bh = blockIdx.x;
    const int b = bh >> 7;
    const int h = bh & 127;
    const int tid = threadIdx.x;

    __shared__ __align__(16) float sG[9 * 128 * 4];
    __shared__ __align__(16) int   sI[9 * 128 * 4];

    for (int item = tid; item < 9 * 128; item += 256) {
        int t = item >> 7;
        int w = item & 127;
        int i = t / 3, j = t - 3 * i;
        int hp = (i == 0) ? h - 1 : h;
        int ip = (i == 0) ? 2 : i - 1;
        int wp = (j == 0) ? w - 1 : w;
        int jp = (j == 0) ? 2 : j - 1;
        float gq[4] = {0.f, 0.f, 0.f, 0.f};
        int id[4] = {-1, -1, -1, -1};
        if (hp >= 0 && wp >= 0) {
            int k = ip * 3 + jp;
            float dxk = (float)(ip - 1);
            float dyk = (float)(jp - 1);
            int obase = ((b * 18 + k) * 128 + hp) * 128 + wp;
            float ox = g_off[obase];
            float oy = g_off[obase + 9 * HW];
            float px = (float)(hp + 1) + dxk + ox;
            float py = (float)(wp + 1) + dyk + oy;
            float fx = floorf(px), fy = floorf(py);
            float ltx = fminf(fmaxf(fx, 0.f), 129.f);
            float lty = fminf(fmaxf(fy, 0.f), 129.f);
            float rbx = fminf(fmaxf(fx + 1.f, 0.f), 129.f);
            float rby = fminf(fmaxf(fy + 1.f, 0.f), 129.f);
            float pxc = fminf(fmaxf(px, 0.f), 129.f);
            float pyc = fminf(fmaxf(py, 0.f), 129.f);
            float gxl = 1.f + (ltx - pxc);
            float gxr = 1.f - (rbx - pxc);
            float gyl = 1.f + (lty - pyc);
            float gyr = 1.f - (rby - pyc);
            float mv = g_m[((b * 9 + k) * 128 + hp) * 128 + wp];
            int ax = (int)ltx - 1, ay = (int)lty - 1;
            int bx = (int)rbx - 1, by = (int)rby - 1;
            if ((unsigned)ax < 128u && (unsigned)ay < 128u) id[0] = ax * 128 + ay;
            if ((unsigned)bx < 128u && (unsigned)by < 128u) id[1] = bx * 128 + by;
            if ((unsigned)ax < 128u && (unsigned)by < 128u) id[2] = ax * 128 + by;
            if ((unsigned)bx < 128u && (unsigned)ay < 128u) id[3] = bx * 128 + ay;
            gq[0] = gxl * gyl * mv;
            gq[1] = gxr * gyr * mv;
            gq[2] = gxl * gyr * mv;
            gq[3] = gxr * gyl * mv;
        }
#pragma unroll
        for (int q = 0; q < 4; q++) {
            sG[(t * 128 + w) * 4 + q] = gq[q];
            sI[(t * 128 + w) * 4 + q] = id[q];
        }
    }
    __syncthreads();

    const int w = tid & 127;
    const int c0 = tid >> 7;        // 0 or 1
    const int rowoff = h * 128 + w;
    const float* psb = g_psff + (size_t)b * OCF * HW + rowoff;

    for (int cc = 0; cc < 32; cc++) {
        int c = cc * 2 + c0;
        const float* xpl = x + (b * C_ + c) * HW;
        float val = 0.f;
#pragma unroll
        for (int t = 0; t < 9; t++) {
            float s = 0.f;
#pragma unroll
            for (int q = 0; q < 4; q++) {
                int idx = sI[(t * 128 + w) * 4 + q];
                if (idx >= 0) s += sG[(t * 128 + w) * 4 + q] * __ldg(&xpl[idx]);
            }
            val += s * psb[(size_t)(c * 9 + t) * HW];
        }
        out[(b * C_ + c) * HW + rowoff] = val;
    }
}

// ---------------------------------------------------------------------------
extern "C" void kernel_launch(void* const* d_in, const int* in_sizes, int n_in,
                              void* d_out, int out_size) {
    const float* feature_size    = (const float*)d_in[0];
    const float* feature_context = (const float*)d_in[1];
    const float* x               = (const float*)d_in[2];
    const float* p_conv_w        = (const float*)d_in[3];
    const float* p_conv_b        = (const float*)d_in[4];
    const float* f_conv_w        = (const float*)d_in[5];
    const float* f_conv_b        = (const float*)d_in[6];
    const float* m_conv_w        = (const float*)d_in[7];
    const float* m_conv_b        = (const float*)d_in[8];
    float* out = (float*)d_out;

    // K0: split/pack f_conv_w to interleaved bf16 hi/lo
    weight_split_kernel<<<(9 * 32 * OCF + 255) / 256, 256>>>(f_conv_w);

    // K1: merged offset(18) + mask(9, sigmoid) conv
    conv_small_merged_kernel<<<B_ * H_, 128>>>(feature_size, p_conv_w, p_conv_b,
                                               m_conv_w, m_conv_b);

    // K2: psffilter conv (576 ch) via tensor cores, smem-staged weights
    dim3 grid2(OCF / 64, B_ * H_);
    conv_big_mma_kernel<<<grid2, 256>>>(feature_context, f_conv_b);

    // K3: sampling + modulate + reduce
    epilogue_kernel<<<B_ * H_, 256>>>(x, out);
}

// round 6
// speedup vs baseline: 1.1192x; 1.1192x over previous
#include <cuda_runtime.h>
#include <cuda_bf16.h>
#include <math.h>
#include <stdint.h>

// Shapes (fixed by setup_inputs)
#define B_  4
#define C_  64
#define H_  128
#define W_  128
#define HW  (H_*W_)          // 16384
#define OCF 576              // f_conv output channels = C*9
#define KTOT 576             // 64*9 reduction size

// Scratch (__device__ globals: allocation-free rule)
__device__ float g_psff[B_ * OCF * HW];   // 151 MB
__device__ float g_off[B_ * 18 * HW];
__device__ float g_m[B_ * 9 * HW];
// packed bf16-split weights: [ (s*32 + icpair) * 576 + oc ], pair packed in .b32
__device__ uint32_t g_wh[9 * 32 * OCF];
__device__ uint32_t g_wl[9 * 32 * OCF];

__device__ __forceinline__ uint32_t pack_bf16(__nv_bfloat16 lo, __nv_bfloat16 hi) {
    uint32_t l = (uint32_t)__bfloat16_as_ushort(lo);
    uint32_t h = (uint32_t)__bfloat16_as_ushort(hi);
    return l | (h << 16);
}

__device__ __forceinline__ void mma_bf16(float* c,
        uint32_t a0, uint32_t a1, uint32_t a2, uint32_t a3,
        uint32_t b0, uint32_t b1) {
    asm volatile(
        "mma.sync.aligned.m16n8k16.row.col.f32.bf16.bf16.f32 "
        "{%0,%1,%2,%3}, {%4,%5,%6,%7}, {%8,%9}, {%0,%1,%2,%3};"
        : "+f"(c[0]), "+f"(c[1]), "+f"(c[2]), "+f"(c[3])
        : "r"(a0), "r"(a1), "r"(a2), "r"(a3), "r"(b0), "r"(b1));
}

// ---------------------------------------------------------------------------
// K0: split f_conv_w into bf16 hi/lo, packed by ic-pairs, k = tap*64 + ic.
// ---------------------------------------------------------------------------
__global__ void weight_split_kernel(const float* __restrict__ wgt) {
    int idx = blockIdx.x * blockDim.x + threadIdx.x;   // over 9*32*576
    if (idx >= 9 * 32 * OCF) return;
    int oc = idx % OCF;
    int tmp = idx / OCF;
    int icp = tmp & 31;
    int s = tmp >> 5;
    float w0 = wgt[oc * KTOT + (2 * icp) * 9 + s];
    float w1 = wgt[oc * KTOT + (2 * icp + 1) * 9 + s];
    __nv_bfloat16 h0 = __float2bfloat16(w0);
    __nv_bfloat16 h1 = __float2bfloat16(w1);
    __nv_bfloat16 l0 = __float2bfloat16(w0 - __bfloat162float(h0));
    __nv_bfloat16 l1 = __float2bfloat16(w1 - __bfloat162float(h1));
    g_wh[idx] = pack_bf16(h0, h1);
    g_wl[idx] = pack_bf16(l0, l1);
}

// ---------------------------------------------------------------------------
// K1: merged small conv3x3: 27 outputs = 18 offset channels + 9 mask (sigmoid).
// One block per (b,h) row, 128 threads (one per w). IC chunked by 16.
// ---------------------------------------------------------------------------
#define OCM  27
#define OCMP 28
__global__ void conv_small_merged_kernel(const float* __restrict__ in,
                                         const float* __restrict__ p_w,
                                         const float* __restrict__ p_b,
                                         const float* __restrict__ m_w,
                                         const float* __restrict__ m_b) {
    const int bh = blockIdx.x;
    const int b = bh >> 7;
    const int h = bh & 127;
    const int tid = threadIdx.x;      // 128 threads, tid == w
    const int w = tid;

    __shared__ __align__(16) float sIn[16 * 3 * 132];
    __shared__ __align__(16) float sW[144 * OCMP];

    float acc[OCMP];
#pragma unroll
    for (int i = 0; i < OCMP; i++) acc[i] = 0.f;

    const float* inb = in + b * C_ * HW;

    for (int chunk = 0; chunk < 4; chunk++) {
        for (int idx = tid; idx < 144 * OCMP; idx += 128) sW[idx] = 0.f;
        __syncthreads();
        for (int idx = tid; idx < 16 * 3 * 130; idx += 128) {
            int ic = idx / 390;
            int rem = idx - ic * 390;
            int r = rem / 130;
            int cc = rem - r * 130;
            int gh = h + r - 1;
            int gw = cc - 1;
            float v = 0.f;
            if ((unsigned)gh < 128u && (unsigned)gw < 128u)
                v = inb[(chunk * 16 + ic) * HW + gh * 128 + gw];
            sIn[(ic * 3 + r) * 132 + cc] = v;
        }
        for (int idx = tid; idx < 144 * OCM; idx += 128) {
            int oc = idx / 144;
            int k = idx - oc * 144;
            float wv = (oc < 18) ? p_w[oc * KTOT + chunk * 144 + k]
                                 : m_w[(oc - 18) * KTOT + chunk * 144 + k];
            sW[k * OCMP + oc] = wv;
        }
        __syncthreads();

#pragma unroll 4
        for (int ic = 0; ic < 16; ic++) {
#pragma unroll
            for (int r = 0; r < 3; r++) {
                float v0 = sIn[(ic * 3 + r) * 132 + w];
                float v1 = sIn[(ic * 3 + r) * 132 + w + 1];
                float v2 = sIn[(ic * 3 + r) * 132 + w + 2];
#pragma unroll
                for (int dw = 0; dw < 3; dw++) {
                    float v = (dw == 0) ? v0 : ((dw == 1) ? v1 : v2);
                    const float4* wp = (const float4*)&sW[(ic * 9 + r * 3 + dw) * OCMP];
#pragma unroll
                    for (int o4 = 0; o4 < OCMP / 4; o4++) {
                        float4 wv = wp[o4];
                        acc[o4 * 4 + 0] += v * wv.x;
                        acc[o4 * 4 + 1] += v * wv.y;
                        acc[o4 * 4 + 2] += v * wv.z;
                        acc[o4 * 4 + 3] += v * wv.w;
                    }
                }
            }
        }
        __syncthreads();
    }

#pragma unroll
    for (int oc = 0; oc < 18; oc++)
        g_off[((b * 18 + oc) * 128 + h) * 128 + w] = acc[oc] + p_b[oc];
#pragma unroll
    for (int oc = 0; oc < 9; oc++) {
        float v = acc[18 + oc] + m_b[oc];
        g_m[((b * 9 + oc) * 128 + h) * 128 + w] = 1.f / (1.f + expf(-v));
    }
}

// ---------------------------------------------------------------------------
// K2: psff conv as bf16-split tensor-core implicit GEMM (R4 structure).
// CTA: one (b,h) row (128 px) x 64 ocs. 8 warps, warp tile 32px x 32oc.
// Activation smem: ic-pair packed bf16 hi/lo tiles, 16 ics per chunk.
// Weights: packed hi/lo .b32 loaded straight from L2 (g_wh/g_wl).
// 3 MMAs per tile: ah*bh + ah*bl + al*bh.
// __launch_bounds__(256,3): force <=85 regs -> 3 CTAs/SM (was 86 -> 2 CTAs).
// ---------------------------------------------------------------------------
#define ROW_STRIDE 136
#define ICP_STRIDE (3 * ROW_STRIDE)   // 408

__global__ __launch_bounds__(256, 3) void conv_big_mma_kernel(
        const float* __restrict__ in,
        const float* __restrict__ bias) {
    const int oc0 = blockIdx.x * 64;          // 9 tiles
    const int bh = blockIdx.y;
    const int b = bh >> 7;
    const int h = bh & 127;
    const int tid = threadIdx.x;
    const int warp = tid >> 5;
    const int lane = tid & 31;
    const int g = lane >> 2;                  // 0..7
    const int t = lane & 3;                   // 0..3
    const int wx = warp & 1;                  // oc half
    const int wy = warp >> 1;                 // px quarter
    const int px0 = wy * 32;
    const int ocb = oc0 + wx * 32;

    __shared__ __align__(16) uint32_t sAh[8 * ICP_STRIDE];
    __shared__ __align__(16) uint32_t sAl[8 * ICP_STRIDE];

    float acc[2][4][4];
#pragma unroll
    for (int mt = 0; mt < 2; mt++)
#pragma unroll
        for (int nt = 0; nt < 4; nt++)
#pragma unroll
            for (int q = 0; q < 4; q++) acc[mt][nt][q] = 0.f;

    const float* inb = in + b * C_ * HW;

    for (int chunk = 0; chunk < 4; chunk++) {
        __syncthreads();
        // stage 16 ics as 8 ic-pairs, bf16 hi/lo packed, 3 rows x 130 padded cols
        for (int idx = tid; idx < 8 * 3 * 130; idx += 256) {
            int icp = idx / 390;
            int rem = idx - icp * 390;
            int r = rem / 130;
            int cc = rem - r * 130;
            int gh = h + r - 1;
            int gw = cc - 1;
            float v0 = 0.f, v1 = 0.f;
            if ((unsigned)gh < 128u && (unsigned)gw < 128u) {
                const float* p = inb + (chunk * 16 + 2 * icp) * HW + gh * 128 + gw;
                v0 = p[0];
                v1 = p[HW];
            }
            __nv_bfloat16 h0 = __float2bfloat16(v0);
            __nv_bfloat16 h1 = __float2bfloat16(v1);
            __nv_bfloat16 l0 = __float2bfloat16(v0 - __bfloat162float(h0));
            __nv_bfloat16 l1 = __float2bfloat16(v1 - __bfloat162float(h1));
            sAh[icp * ICP_STRIDE + r * ROW_STRIDE + cc] = pack_bf16(h0, h1);
            sAl[icp * ICP_STRIDE + r * ROW_STRIDE + cc] = pack_bf16(l0, l1);
        }
        __syncthreads();

#pragma unroll
        for (int s = 0; s < 9; s++) {
            const int r = s / 3;
            const int dw = s - 3 * r;
            // A fragments (activations), 2 m-tiles, hi + lo
            uint32_t ah[2][4], al[2][4];
#pragma unroll
            for (int mt = 0; mt < 2; mt++) {
                int cb = px0 + mt * 16 + g + dw;
                int base_lo = t * ICP_STRIDE + r * ROW_STRIDE + cb;
                int base_hi = (t + 4) * ICP_STRIDE + r * ROW_STRIDE + cb;
                ah[mt][0] = sAh[base_lo];
                ah[mt][1] = sAh[base_lo + 8];
                ah[mt][2] = sAh[base_hi];
                ah[mt][3] = sAh[base_hi + 8];
                al[mt][0] = sAl[base_lo];
                al[mt][1] = sAl[base_lo + 8];
                al[mt][2] = sAl[base_hi];
                al[mt][3] = sAl[base_hi + 8];
            }
#pragma unroll
            for (int nt = 0; nt < 4; nt++) {
                int widx = (s * 32 + chunk * 8 + t) * OCF + ocb + nt * 8 + g;
                uint32_t bh0 = g_wh[widx];
                uint32_t bh1 = g_wh[widx + 4 * OCF];
                uint32_t bl0 = g_wl[widx];
                uint32_t bl1 = g_wl[widx + 4 * OCF];
#pragma unroll
                for (int mt = 0; mt < 2; mt++) {
                    mma_bf16(acc[mt][nt], ah[mt][0], ah[mt][1], ah[mt][2], ah[mt][3], bh0, bh1);
                    mma_bf16(acc[mt][nt], ah[mt][0], ah[mt][1], ah[mt][2], ah[mt][3], bl0, bl1);
                    mma_bf16(acc[mt][nt], al[mt][0], al[mt][1], al[mt][2], al[mt][3], bh0, bh1);
                }
            }
        }
    }

    // epilogue: add bias, store to g_psff[oc][b,h,px]
    float* psb = g_psff + (size_t)b * OCF * HW + h * 128;
#pragma unroll
    for (int nt = 0; nt < 4; nt++) {
        int oc_a = ocb + nt * 8 + 2 * t;
        int oc_b = oc_a + 1;
        float bva = __ldg(&bias[oc_a]);
        float bvb = __ldg(&bias[oc_b]);
#pragma unroll
        for (int mt = 0; mt < 2; mt++) {
            int px = px0 + mt * 16 + g;
            psb[(size_t)oc_a * HW + px]     = acc[mt][nt][0] + bva;
            psb[(size_t)oc_b * HW + px]     = acc[mt][nt][1] + bvb;
            psb[(size_t)oc_a * HW + px + 8] = acc[mt][nt][2] + bva;
            psb[(size_t)oc_b * HW + px + 8] = acc[mt][nt][3] + bvb;
        }
    }
}

// ---------------------------------------------------------------------------
// K3: deformable sampling + modulation + 9-term reduce.
// ---------------------------------------------------------------------------
__global__ __launch_bounds__(256) void epilogue_kernel(
        const float* __restrict__ x,
        float* __restrict__ out) {
    const int bh = blockIdx.x;
    const int b = bh >> 7;
    const int h = bh & 127;
    const int tid = threadIdx.x;

    __shared__ __align__(16) float sG[9 * 128 * 4];
    __shared__ __align__(16) int   sI[9 * 128 * 4];

    for (int item = tid; item < 9 * 128; item += 256) {
        int t = item >> 7;
        int w = item & 127;
        int i = t / 3, j = t - 3 * i;
        int hp = (i == 0) ? h - 1 : h;
        int ip = (i == 0) ? 2 : i - 1;
        int wp = (j == 0) ? w - 1 : w;
        int jp = (j == 0) ? 2 : j - 1;
        float gq[4] = {0.f, 0.f, 0.f, 0.f};
        int id[4] = {-1, -1, -1, -1};
        if (hp >= 0 && wp >= 0) {
            int k = ip * 3 + jp;
            float dxk = (float)(ip - 1);
            float dyk = (float)(jp - 1);
            int obase = ((b * 18 + k) * 128 + hp) * 128 + wp;
            float ox = g_off[obase];
            float oy = g_off[obase + 9 * HW];
            float px = (float)(hp + 1) + dxk + ox;
            float py = (float)(wp + 1) + dyk + oy;
            float fx = floorf(px), fy = floorf(py);
            float ltx = fminf(fmaxf(fx, 0.f), 129.f);
            float lty = fminf(fmaxf(fy, 0.f), 129.f);
            float rbx = fminf(fmaxf(fx + 1.f, 0.f), 129.f);
            float rby = fminf(fmaxf(fy + 1.f, 0.f), 129.f);
            float pxc = fminf(fmaxf(px, 0.f), 129.f);
            float pyc = fminf(fmaxf(py, 0.f), 129.f);
            float gxl = 1.f + (ltx - pxc);
            float gxr = 1.f - (rbx - pxc);
            float gyl = 1.f + (lty - pyc);
            float gyr = 1.f - (rby - pyc);
            float mv = g_m[((b * 9 + k) * 128 + hp) * 128 + wp];
            int ax = (int)ltx - 1, ay = (int)lty - 1;
            int bx = (int)rbx - 1, by = (int)rby - 1;
            if ((unsigned)ax < 128u && (unsigned)ay < 128u) id[0] = ax * 128 + ay;
            if ((unsigned)bx < 128u && (unsigned)by < 128u) id[1] = bx * 128 + by;
            if ((unsigned)ax < 128u && (unsigned)by < 128u) id[2] = ax * 128 + by;
            if ((unsigned)bx < 128u && (unsigned)ay < 128u) id[3] = bx * 128 + ay;
            gq[0] = gxl * gyl * mv;
            gq[1] = gxr * gyr * mv;
            gq[2] = gxl * gyr * mv;
            gq[3] = gxr * gyl * mv;
        }
#pragma unroll
        for (int q = 0; q < 4; q++) {
            sG[(t * 128 + w) * 4 + q] = gq[q];
            sI[(t * 128 + w) * 4 + q] = id[q];
        }
    }
    __syncthreads();

    const int w = tid & 127;
    const int c0 = tid >> 7;        // 0 or 1
    const int rowoff = h * 128 + w;
    const float* psb = g_psff + (size_t)b * OCF * HW + rowoff;

    for (int cc = 0; cc < 32; cc++) {
        int c = cc * 2 + c0;
        const float* xpl = x + (b * C_ + c) * HW;
        float val = 0.f;
#pragma unroll
        for (int t = 0; t < 9; t++) {
            float s = 0.f;
#pragma unroll
            for (int q = 0; q < 4; q++) {
                int idx = sI[(t * 128 + w) * 4 + q];
                if (idx >= 0) s += sG[(t * 128 + w) * 4 + q] * __ldg(&xpl[idx]);
            }
            val += s * psb[(size_t)(c * 9 + t) * HW];
        }
        out[(b * C_ + c) * HW + rowoff] = val;
    }
}

// ---------------------------------------------------------------------------
extern "C" void kernel_launch(void* const* d_in, const int* in_sizes, int n_in,
                              void* d_out, int out_size) {
    const float* feature_size    = (const float*)d_in[0];
    const float* feature_context = (const float*)d_in[1];
    const float* x               = (const float*)d_in[2];
    const float* p_conv_w        = (const float*)d_in[3];
    const float* p_conv_b        = (const float*)d_in[4];
    const float* f_conv_w        = (const float*)d_in[5];
    const float* f_conv_b        = (const float*)d_in[6];
    const float* m_conv_w        = (const float*)d_in[7];
    const float* m_conv_b        = (const float*)d_in[8];
    float* out = (float*)d_out;

    // K0: split/pack f_conv_w to bf16 hi/lo
    weight_split_kernel<<<(9 * 32 * OCF + 255) / 256, 256>>>(f_conv_w);

    // K1: merged offset(18) + mask(9, sigmoid) conv
    conv_small_merged_kernel<<<B_ * H_, 128>>>(feature_size, p_conv_w, p_conv_b,
                                               m_conv_w, m_conv_b);

    // K2: psffilter conv (576 ch) via tensor cores
    dim3 grid2(OCF / 64, B_ * H_);
    conv_big_mma_kernel<<<grid2, 256>>>(feature_context, f_conv_b);

    // K3: sampling + modulate + reduce
    epilogue_kernel<<<B_ * H_, 256>>>(x, out);
}

// round 9
// speedup vs baseline: 1.1320x; 1.0114x over previous
#include <cuda_runtime.h>
#include <cuda_bf16.h>
#include <math.h>
#include <stdint.h>

// Shapes (fixed by setup_inputs)
#define B_  4
#define C_  64
#define H_  128
#define W_  128
#define HW  (H_*W_)          // 16384
#define OCF 576              // f_conv output channels = C*9
#define KTOT 576             // 64*9 reduction size

// Scratch (__device__ globals: allocation-free rule)
__device__ float g_psff[B_ * OCF * HW];   // 151 MB
__device__ float g_off[B_ * 18 * HW];
__device__ float g_m[B_ * 9 * HW];
// packed bf16-split weights: [ (s*32 + icpair) * 576 + oc ], pair packed in .b32
__device__ uint32_t g_wh[9 * 32 * OCF];
__device__ uint32_t g_wl[9 * 32 * OCF];

__device__ __forceinline__ uint32_t pack_bf16(__nv_bfloat16 lo, __nv_bfloat16 hi) {
    uint32_t l = (uint32_t)__bfloat16_as_ushort(lo);
    uint32_t h = (uint32_t)__bfloat16_as_ushort(hi);
    return l | (h << 16);
}

__device__ __forceinline__ void mma_bf16(float* c,
        uint32_t a0, uint32_t a1, uint32_t a2, uint32_t a3,
        uint32_t b0, uint32_t b1) {
    asm volatile(
        "mma.sync.aligned.m16n8k16.row.col.f32.bf16.bf16.f32 "
        "{%0,%1,%2,%3}, {%4,%5,%6,%7}, {%8,%9}, {%0,%1,%2,%3};"
        : "+f"(c[0]), "+f"(c[1]), "+f"(c[2]), "+f"(c[3])
        : "r"(a0), "r"(a1), "r"(a2), "r"(a3), "r"(b0), "r"(b1));
}

// ---------------------------------------------------------------------------
// K0: split f_conv_w into bf16 hi/lo, packed by ic-pairs, k = tap*64 + ic.
// ---------------------------------------------------------------------------
__global__ void weight_split_kernel(const float* __restrict__ wgt) {
    int idx = blockIdx.x * blockDim.x + threadIdx.x;   // over 9*32*576
    if (idx >= 9 * 32 * OCF) return;
    int oc = idx % OCF;
    int tmp = idx / OCF;
    int icp = tmp & 31;
    int s = tmp >> 5;
    float w0 = wgt[oc * KTOT + (2 * icp) * 9 + s];
    float w1 = wgt[oc * KTOT + (2 * icp + 1) * 9 + s];
    __nv_bfloat16 h0 = __float2bfloat16(w0);
    __nv_bfloat16 h1 = __float2bfloat16(w1);
    __nv_bfloat16 l0 = __float2bfloat16(w0 - __bfloat162float(h0));
    __nv_bfloat16 l1 = __float2bfloat16(w1 - __bfloat162float(h1));
    g_wh[idx] = pack_bf16(h0, h1);
    g_wl[idx] = pack_bf16(l0, l1);
}

// ---------------------------------------------------------------------------
// K1: merged small conv3x3: 27 outputs = 18 offset channels + 9 mask (sigmoid).
// ---------------------------------------------------------------------------
#define OCM  27
#define OCMP 28
__global__ void conv_small_merged_kernel(const float* __restrict__ in,
                                         const float* __restrict__ p_w,
                                         const float* __restrict__ p_b,
                                         const float* __restrict__ m_w,
                                         const float* __restrict__ m_b) {
    const int bh = blockIdx.x;
    const int b = bh >> 7;
    const int h = bh & 127;
    const int tid = threadIdx.x;      // 128 threads, tid == w
    const int w = tid;

    __shared__ __align__(16) float sIn[16 * 3 * 132];
    __shared__ __align__(16) float sW[144 * OCMP];

    float acc[OCMP];
#pragma unroll
    for (int i = 0; i < OCMP; i++) acc[i] = 0.f;

    const float* inb = in + b * C_ * HW;

    for (int chunk = 0; chunk < 4; chunk++) {
        for (int idx = tid; idx < 144 * OCMP; idx += 128) sW[idx] = 0.f;
        __syncthreads();
        for (int idx = tid; idx < 16 * 3 * 130; idx += 128) {
            int ic = idx / 390;
            int rem = idx - ic * 390;
            int r = rem / 130;
            int cc = rem - r * 130;
            int gh = h + r - 1;
            int gw = cc - 1;
            float v = 0.f;
            if ((unsigned)gh < 128u && (unsigned)gw < 128u)
                v = inb[(chunk * 16 + ic) * HW + gh * 128 + gw];
            sIn[(ic * 3 + r) * 132 + cc] = v;
        }
        for (int idx = tid; idx < 144 * OCM; idx += 128) {
            int oc = idx / 144;
            int k = idx - oc * 144;
            float wv = (oc < 18) ? p_w[oc * KTOT + chunk * 144 + k]
                                 : m_w[(oc - 18) * KTOT + chunk * 144 + k];
            sW[k * OCMP + oc] = wv;
        }
        __syncthreads();

#pragma unroll 4
        for (int ic = 0; ic < 16; ic++) {
#pragma unroll
            for (int r = 0; r < 3; r++) {
                float v0 = sIn[(ic * 3 + r) * 132 + w];
                float v1 = sIn[(ic * 3 + r) * 132 + w + 1];
                float v2 = sIn[(ic * 3 + r) * 132 + w + 2];
#pragma unroll
                for (int dw = 0; dw < 3; dw++) {
                    float v = (dw == 0) ? v0 : ((dw == 1) ? v1 : v2);
                    const float4* wp = (const float4*)&sW[(ic * 9 + r * 3 + dw) * OCMP];
#pragma unroll
                    for (int o4 = 0; o4 < OCMP / 4; o4++) {
                        float4 wv = wp[o4];
                        acc[o4 * 4 + 0] += v * wv.x;
                        acc[o4 * 4 + 1] += v * wv.y;
                        acc[o4 * 4 + 2] += v * wv.z;
                        acc[o4 * 4 + 3] += v * wv.w;
                    }
                }
            }
        }
        __syncthreads();
    }

#pragma unroll
    for (int oc = 0; oc < 18; oc++)
        g_off[((b * 18 + oc) * 128 + h) * 128 + w] = acc[oc] + p_b[oc];
#pragma unroll
    for (int oc = 0; oc < 9; oc++) {
        float v = acc[18 + oc] + m_b[oc];
        g_m[((b * 9 + oc) * 128 + h) * 128 + w] = 1.f / (1.f + expf(-v));
    }
}

// ---------------------------------------------------------------------------
// K2: psff conv as bf16-split tensor-core implicit GEMM.
// CTA: one (b,h) row (128 px) x 64 ocs. 8 warps, warp tile 32px x 32oc.
// B fragments batched at tap start (MLP=16) before A LDS + 24 MMAs.
// __launch_bounds__(256,3): <=85 regs -> 3 CTAs/SM.
// ---------------------------------------------------------------------------
#define ROW_STRIDE 136
#define ICP_STRIDE (3 * ROW_STRIDE)   // 408

__global__ __launch_bounds__(256, 3) void conv_big_mma_kernel(
        const float* __restrict__ in,
        const float* __restrict__ bias) {
    const int oc0 = blockIdx.x * 64;          // 9 tiles
    const int bh = blockIdx.y;
    const int b = bh >> 7;
    const int h = bh & 127;
    const int tid = threadIdx.x;
    const int warp = tid >> 5;
    const int lane = tid & 31;
    const int g = lane >> 2;                  // 0..7
    const int t = lane & 3;                   // 0..3
    const int wx = warp & 1;                  // oc half
    const int wy = warp >> 1;                 // px quarter
    const int px0 = wy * 32;
    const int ocb = oc0 + wx * 32;

    __shared__ __align__(16) uint32_t sAh[8 * ICP_STRIDE];
    __shared__ __align__(16) uint32_t sAl[8 * ICP_STRIDE];

    float acc[2][4][4];
#pragma unroll
    for (int mt = 0; mt < 2; mt++)
#pragma unroll
        for (int nt = 0; nt < 4; nt++)
#pragma unroll
            for (int q = 0; q < 4; q++) acc[mt][nt][q] = 0.f;

    const float* inb = in + b * C_ * HW;

    for (int chunk = 0; chunk < 4; chunk++) {
        __syncthreads();
        // stage 16 ics as 8 ic-pairs, bf16 hi/lo packed, 3 rows x 130 padded cols
        for (int idx = tid; idx < 8 * 3 * 130; idx += 256) {
            int icp = idx / 390;
            int rem = idx - icp * 390;
            int r = rem / 130;
            int cc = rem - r * 130;
            int gh = h + r - 1;
            int gw = cc - 1;
            float v0 = 0.f, v1 = 0.f;
            if ((unsigned)gh < 128u && (unsigned)gw < 128u) {
                const float* p = inb + (chunk * 16 + 2 * icp) * HW + gh * 128 + gw;
                v0 = p[0];
                v1 = p[HW];
            }
            __nv_bfloat16 h0 = __float2bfloat16(v0);
            __nv_bfloat16 h1 = __float2bfloat16(v1);
            __nv_bfloat16 l0 = __float2bfloat16(v0 - __bfloat162float(h0));
            __nv_bfloat16 l1 = __float2bfloat16(v1 - __bfloat162float(h1));
            sAh[icp * ICP_STRIDE + r * ROW_STRIDE + cc] = pack_bf16(h0, h1);
            sAl[icp * ICP_STRIDE + r * ROW_STRIDE + cc] = pack_bf16(l0, l1);
        }
        __syncthreads();

#pragma unroll
        for (int s = 0; s < 9; s++) {
            const int r = s / 3;
            const int dw = s - 3 * r;

            // batch ALL B-fragment loads for this tap first (MLP=16)
            uint32_t bhr[4][2], blr[4][2];
#pragma unroll
            for (int nt = 0; nt < 4; nt++) {
                int widx = (s * 32 + chunk * 8 + t) * OCF + ocb + nt * 8 + g;
                bhr[nt][0] = g_wh[widx];
                bhr[nt][1] = g_wh[widx + 4 * OCF];
                blr[nt][0] = g_wl[widx];
                blr[nt][1] = g_wl[widx + 4 * OCF];
            }

            // A fragments (activations), 2 m-tiles, hi + lo
            uint32_t ah[2][4], al[2][4];
#pragma unroll
            for (int mt = 0; mt < 2; mt++) {
                int cb = px0 + mt * 16 + g + dw;
                int base_lo = t * ICP_STRIDE + r * ROW_STRIDE + cb;
                int base_hi = (t + 4) * ICP_STRIDE + r * ROW_STRIDE + cb;
                ah[mt][0] = sAh[base_lo];
                ah[mt][1] = sAh[base_lo + 8];
                ah[mt][2] = sAh[base_hi];
                ah[mt][3] = sAh[base_hi + 8];
                al[mt][0] = sAl[base_lo];
                al[mt][1] = sAl[base_lo + 8];
                al[mt][2] = sAl[base_hi];
                al[mt][3] = sAl[base_hi + 8];
            }

#pragma unroll
            for (int nt = 0; nt < 4; nt++) {
#pragma unroll
                for (int mt = 0; mt < 2; mt++) {
                    mma_bf16(acc[mt][nt], ah[mt][0], ah[mt][1], ah[mt][2], ah[mt][3], bhr[nt][0], bhr[nt][1]);
                    mma_bf16(acc[mt][nt], ah[mt][0], ah[mt][1], ah[mt][2], ah[mt][3], blr[nt][0], blr[nt][1]);
                    mma_bf16(acc[mt][nt], al[mt][0], al[mt][1], al[mt][2], al[mt][3], bhr[nt][0], bhr[nt][1]);
                }
            }
        }
    }

    // epilogue: add bias, store to g_psff[oc][b,h,px]
    float* psb = g_psff + (size_t)b * OCF * HW + h * 128;
#pragma unroll
    for (int nt = 0; nt < 4; nt++) {
        int oc_a = ocb + nt * 8 + 2 * t;
        int oc_b = oc_a + 1;
        float bva = __ldg(&bias[oc_a]);
        float bvb = __ldg(&bias[oc_b]);
#pragma unroll
        for (int mt = 0; mt < 2; mt++) {
            int px = px0 + mt * 16 + g;
            psb[(size_t)oc_a * HW + px]     = acc[mt][nt][0] + bva;
            psb[(size_t)oc_b * HW + px]     = acc[mt][nt][1] + bvb;
            psb[(size_t)oc_a * HW + px + 8] = acc[mt][nt][2] + bva;
            psb[(size_t)oc_b * HW + px + 8] = acc[mt][nt][3] + bvb;
        }
    }
}

// ---------------------------------------------------------------------------
// K3: deformable sampling + modulation + 9-term reduce, loop-inverted.
// Thread = (c_half, w): 32-channel register accumulator; per-t tables loaded
// ONCE per t as int4/float4 and held in registers across the channel loop.
// ---------------------------------------------------------------------------
__global__ __launch_bounds__(256) void epilogue_kernel(
        const float* __restrict__ x,
        float* __restrict__ out) {
    const int bh = blockIdx.x;
    const int b = bh >> 7;
    const int h = bh & 127;
    const int tid = threadIdx.x;

    __shared__ __align__(16) float sG[9 * 128 * 4];
    __shared__ __align__(16) int   sI[9 * 128 * 4];

    for (int item = tid; item < 9 * 128; item += 256) {
        int t = item >> 7;
        int w = item & 127;
        int i = t / 3, j = t - 3 * i;
        int hp = (i == 0) ? h - 1 : h;
        int ip = (i == 0) ? 2 : i - 1;
        int wp = (j == 0) ? w - 1 : w;
        int jp = (j == 0) ? 2 : j - 1;
        float gq[4] = {0.f, 0.f, 0.f, 0.f};
        int id[4] = {-1, -1, -1, -1};
        if (hp >= 0 && wp >= 0) {
            int k = ip * 3 + jp;
            float dxk = (float)(ip - 1);
            float dyk = (float)(jp - 1);
            int obase = ((b * 18 + k) * 128 + hp) * 128 + wp;
            float ox = g_off[obase];
            float oy = g_off[obase + 9 * HW];
            float px = (float)(hp + 1) + dxk + ox;
            float py = (float)(wp + 1) + dyk + oy;
            float fx = floorf(px), fy = floorf(py);
            float ltx = fminf(fmaxf(fx, 0.f), 129.f);
            float lty = fminf(fmaxf(fy, 0.f), 129.f);
            float rbx = fminf(fmaxf(fx + 1.f, 0.f), 129.f);
            float rby = fminf(fmaxf(fy + 1.f, 0.f), 129.f);
            float pxc = fminf(fmaxf(px, 0.f), 129.f);
            float pyc = fminf(fmaxf(py, 0.f), 129.f);
            float gxl = 1.f + (ltx - pxc);
            float gxr = 1.f - (rbx - pxc);
            float gyl = 1.f + (lty - pyc);
            float gyr = 1.f - (rby - pyc);
            float mv = g_m[((b * 9 + k) * 128 + hp) * 128 + wp];
            int ax = (int)ltx - 1, ay = (int)lty - 1;
            int bx = (int)rbx - 1, by = (int)rby - 1;
            if ((unsigned)ax < 128u && (unsigned)ay < 128u) id[0] = ax * 128 + ay;
            if ((unsigned)bx < 128u && (unsigned)by < 128u) id[1] = bx * 128 + by;
            if ((unsigned)ax < 128u && (unsigned)by < 128u) id[2] = ax * 128 + by;
            if ((unsigned)bx < 128u && (unsigned)ay < 128u) id[3] = bx * 128 + ay;
            gq[0] = gxl * gyl * mv;
            gq[1] = gxr * gyr * mv;
            gq[2] = gxl * gyr * mv;
            gq[3] = gxr * gyl * mv;
        }
#pragma unroll
        for (int q = 0; q < 4; q++) {
            sG[(t * 128 + w) * 4 + q] = gq[q];
            sI[(t * 128 + w) * 4 + q] = id[q];
        }
    }
    __syncthreads();

    const int w = tid & 127;
    const int c0 = (tid >> 7) * 32;   // 0 or 32
    const int rowoff = h * 128 + w;
    const float* xb = x + (size_t)(b * C_ + c0) * HW;
    const float* psb = g_psff + (size_t)b * OCF * HW + rowoff;

    float acc[32];
#pragma unroll
    for (int j = 0; j < 32; j++) acc[j] = 0.f;

#pragma unroll
    for (int t = 0; t < 9; t++) {
        const int4   id4 = *(const int4*)  &sI[(t * 128 + w) * 4];
        const float4 g4  = *(const float4*)&sG[(t * 128 + w) * 4];
        const float* pscol = psb + (size_t)(c0 * 9 + t) * HW;
        const float* xpl = xb;
#pragma unroll 8
        for (int j = 0; j < 32; j++) {
            float s = 0.f;
            if (id4.x >= 0) s += g4.x * __ldg(xpl + id4.x);
            if (id4.y >= 0) s += g4.y * __ldg(xpl + id4.y);
            if (id4.z >= 0) s += g4.z * __ldg(xpl + id4.z);
            if (id4.w >= 0) s += g4.w * __ldg(xpl + id4.w);
            acc[j] += s * __ldg(pscol);
            pscol += 9 * HW;
            xpl += HW;
        }
    }

    float* ob = out + (size_t)(b * C_ + c0) * HW + rowoff;
#pragma unroll
    for (int j = 0; j < 32; j++)
        ob[(size_t)j * HW] = acc[j];
}

// ---------------------------------------------------------------------------
extern "C" void kernel_launch(void* const* d_in, const int* in_sizes, int n_in,
                              void* d_out, int out_size) {
    const float* feature_size    = (const float*)d_in[0];
    const float* feature_context = (const float*)d_in[1];
    const float* x               = (const float*)d_in[2];
    const float* p_conv_w        = (const float*)d_in[3];
    const float* p_conv_b        = (const float*)d_in[4];
    const float* f_conv_w        = (const float*)d_in[5];
    const float* f_conv_b        = (const float*)d_in[6];
    const float* m_conv_w        = (const float*)d_in[7];
    const float* m_conv_b        = (const float*)d_in[8];
    float* out = (float*)d_out;

    // K0: split/pack f_conv_w to bf16 hi/lo
    weight_split_kernel<<<(9 * 32 * OCF + 255) / 256, 256>>>(f_conv_w);

    // K1: merged offset(18) + mask(9, sigmoid) conv
    conv_small_merged_kernel<<<B_ * H_, 128>>>(feature_size, p_conv_w, p_conv_b,
                                               m_conv_w, m_conv_b);

    // K2: psffilter conv (576 ch) via tensor cores
    dim3 grid2(OCF / 64, B_ * H_);
    conv_big_mma_kernel<<<grid2, 256>>>(feature_context, f_conv_b);

    // K3: sampling + modulate + reduce
    epilogue_kernel<<<B_ * H_, 256>>>(x, out);
}